// round 15
// baseline (speedup 1.0000x reference)
#include <cuda_runtime.h>

#define NPTS   800000
#define EPSV   1e-5f

// ---------------- scratch (device globals; no allocation allowed) ----------
__device__ float g_h1[NPTS * 64];   // relu(bn(feats@w1+b1))          204.8 MB
__device__ float g_z2[NPTS * 64];   // subm3x3(h1) (raw, no b2)       204.8 MB

// accumulators, zeroed at the start of every launch
// [0,64)      colsum(feats)
// [64,4160)   gram(feats)        = feats^T feats
// [4160,4224) colsum(z2)
// [4224,4288) colsumsq(z2)
// [4288,4352) colsum(h2)
// [4352,8448) gram(h2)
__device__ float g_acc[8448];

// per-channel fused BN params: y = x*sc + sh   (bias folded in)
__device__ float g_sc1[64],  g_sh1[64];
__device__ float g_scs[256], g_shs[256];
__device__ float g_sc2[64],  g_sh2[64];
__device__ float g_sc3[256], g_sh3[256];

// ---------------------------------------------------------------------------
__global__ void k_zero()
{
    int i = blockIdx.x * 256 + threadIdx.x;
    if (i < 8448) g_acc[i] = 0.0f;
}

// ---------------------------------------------------------------------------
// colsum + Gram of a [N,64] matrix.
// mode 0: X = feats (argument).  mode 1: X = relu(g_z2*sc2+sh2)  (h2).
__global__ void __launch_bounds__(256) k_stats64(const float* __restrict__ X, int mode)
{
    __shared__ float sX[16][65];
    __shared__ float ssc[64], ssh[64];

    float* outSum  = mode ? &g_acc[4288] : &g_acc[0];
    float* outGram = mode ? &g_acc[4352] : &g_acc[64];
    const float* src = mode ? g_z2 : X;

    int tid = threadIdx.x;
    int tx = tid & 15, ty = tid >> 4;
    int lr = tid >> 4, seg = tid & 15;

    if (mode && tid < 64) { ssc[tid] = g_sc2[tid]; ssh[tid] = g_sh2[tid]; }
    __syncthreads();

    float acc[4][4];
    float cs[4];
#pragma unroll
    for (int i = 0; i < 4; i++) {
        cs[i] = 0.f;
#pragma unroll
        for (int j = 0; j < 4; j++) acc[i][j] = 0.f;
    }

    int rowBase = blockIdx.x * 1024;
    for (int chunk = 0; chunk < 1024; chunk += 16) {
        int r = rowBase + chunk + lr;
        float4 v = make_float4(0.f, 0.f, 0.f, 0.f);
        if (r < NPTS) v = reinterpret_cast<const float4*>(src)[r * 16 + seg];
        if (mode) {
            int c = seg * 4;
            v.x = fmaxf(fmaf(v.x, ssc[c + 0], ssh[c + 0]), 0.f);
            v.y = fmaxf(fmaf(v.y, ssc[c + 1], ssh[c + 1]), 0.f);
            v.z = fmaxf(fmaf(v.z, ssc[c + 2], ssh[c + 2]), 0.f);
            v.w = fmaxf(fmaf(v.w, ssc[c + 3], ssh[c + 3]), 0.f);
        }
        __syncthreads();
        sX[lr][seg * 4 + 0] = v.x; sX[lr][seg * 4 + 1] = v.y;
        sX[lr][seg * 4 + 2] = v.z; sX[lr][seg * 4 + 3] = v.w;
        __syncthreads();
#pragma unroll
        for (int rr = 0; rr < 16; rr++) {
            float a0 = sX[rr][ty * 4 + 0], a1 = sX[rr][ty * 4 + 1];
            float a2 = sX[rr][ty * 4 + 2], a3 = sX[rr][ty * 4 + 3];
            float b0 = sX[rr][tx * 4 + 0], b1 = sX[rr][tx * 4 + 1];
            float b2 = sX[rr][tx * 4 + 2], b3 = sX[rr][tx * 4 + 3];
            acc[0][0] = fmaf(a0, b0, acc[0][0]); acc[0][1] = fmaf(a0, b1, acc[0][1]);
            acc[0][2] = fmaf(a0, b2, acc[0][2]); acc[0][3] = fmaf(a0, b3, acc[0][3]);
            acc[1][0] = fmaf(a1, b0, acc[1][0]); acc[1][1] = fmaf(a1, b1, acc[1][1]);
            acc[1][2] = fmaf(a1, b2, acc[1][2]); acc[1][3] = fmaf(a1, b3, acc[1][3]);
            acc[2][0] = fmaf(a2, b0, acc[2][0]); acc[2][1] = fmaf(a2, b1, acc[2][1]);
            acc[2][2] = fmaf(a2, b2, acc[2][2]); acc[2][3] = fmaf(a2, b3, acc[2][3]);
            acc[3][0] = fmaf(a3, b0, acc[3][0]); acc[3][1] = fmaf(a3, b1, acc[3][1]);
            acc[3][2] = fmaf(a3, b2, acc[3][2]); acc[3][3] = fmaf(a3, b3, acc[3][3]);
            if (ty == 0) { cs[0] += b0; cs[1] += b1; cs[2] += b2; cs[3] += b3; }
        }
    }
#pragma unroll
    for (int i = 0; i < 4; i++)
#pragma unroll
        for (int j = 0; j < 4; j++)
            atomicAdd(&outGram[(ty * 4 + i) * 64 + (tx * 4 + j)], acc[i][j]);
    if (ty == 0) {
#pragma unroll
        for (int j = 0; j < 4; j++) atomicAdd(&outSum[tx * 4 + j], cs[j]);
    }
}

// ---------------------------------------------------------------------------
// Analytic BN params for Z = X@w + b from Gram/colsum of X.
// which 0: feats-stats -> (w1,...) J=64 -> sc1/sh1
// which 1: feats-stats -> (ws,...) J=256 -> scs/shs
// which 2: h2-stats    -> (w3,...) J=256 -> sc3/sh3
__global__ void k_params_lin(int which, int J,
                             const float* __restrict__ w, const float* __restrict__ b,
                             const float* __restrict__ g, const float* __restrict__ be)
{
    __shared__ float sG[4096];
    __shared__ float sMu[64];
    const float* gram = (which == 2) ? &g_acc[4352] : &g_acc[64];
    const float* csum = (which == 2) ? &g_acc[4288] : &g_acc[0];
    float* sc = (which == 0) ? g_sc1 : (which == 1) ? g_scs : g_sc3;
    float* sh = (which == 0) ? g_sh1 : (which == 1) ? g_shs : g_sh3;

    int tid = threadIdx.x;
    for (int i = tid; i < 4096; i += blockDim.x) sG[i] = gram[i];
    if (tid < 64) sMu[tid] = csum[tid] * (1.0f / (float)NPTS);
    __syncthreads();

    for (int j = tid; j < J; j += blockDim.x) {
        float wj[64];
        for (int c = 0; c < 64; c++) wj[c] = w[c * J + j];
        float mw = 0.f;
        for (int c = 0; c < 64; c++) mw = fmaf(sMu[c], wj[c], mw);
        float q = 0.f;
        for (int c = 0; c < 64; c++) {
            float t = 0.f;
            for (int d = 0; d < 64; d++) t = fmaf(sG[c * 64 + d], wj[d], t);
            q = fmaf(t, wj[c], q);
        }
        q *= (1.0f / (float)NPTS);
        float bj = b[j];
        float m = mw + bj;
        float ex2 = q + 2.f * bj * mw + bj * bj;
        float var = ex2 - m * m;
        float scale = g[j] * rsqrtf(var + EPSV);
        sc[j] = scale;
        sh[j] = be[j] + (bj - m) * scale;
    }
}

// BN params for z2 (stats accumulated directly; b2 folded analytically)
__global__ void k_params2(const float* __restrict__ b2, const float* __restrict__ g2,
                          const float* __restrict__ be2)
{
    int j = threadIdx.x;
    if (j < 64) {
        float inv = 1.0f / (float)NPTS;
        float mean = g_acc[4160 + j] * inv;                 // mean of raw z2
        float var  = g_acc[4224 + j] * inv - mean * mean;   // var unaffected by +b2
        float scale = g2[j] * rsqrtf(var + EPSV);
        g_sc2[j] = scale;
        g_sh2[j] = be2[j] - mean * scale;   // applied to raw z2 == bn(z2+b2)
        (void)b2;
    }
}

// ---------------------------------------------------------------------------
// h1 = relu(bn(feats@w1 + b1)) ; bn folded into sc1/sh1.  Tile 128x64.
__global__ void __launch_bounds__(256) k_gemm1(const float* __restrict__ X,
                                               const float* __restrict__ W)
{
    extern __shared__ float dyn[];
    float* sW = dyn;                               // 64x64
    float (*sX)[65] = (float(*)[65])(dyn + 4096);  // 128x65
    float* ssc = dyn + 4096 + 128 * 65;
    float* ssh = ssc + 64;

    int tid = threadIdx.x;
    if (tid < 64) { ssc[tid] = g_sc1[tid]; ssh[tid] = g_sh1[tid]; }
    for (int i = tid; i < 1024; i += 256)
        ((float4*)sW)[i] = ((const float4*)W)[i];

    int row0 = blockIdx.x * 128;
    for (int e = tid; e < 2048; e += 256) {
        int r = e >> 4, s = e & 15;
        float4 v = ((const float4*)X)[(row0 + r) * 16 + s];
        sX[r][s * 4 + 0] = v.x; sX[r][s * 4 + 1] = v.y;
        sX[r][s * 4 + 2] = v.z; sX[r][s * 4 + 3] = v.w;
    }
    __syncthreads();

    int tx = tid & 15, ty = tid >> 4;
    float acc[8][4];
#pragma unroll
    for (int r = 0; r < 8; r++) { acc[r][0]=0;acc[r][1]=0;acc[r][2]=0;acc[r][3]=0; }

#pragma unroll 4
    for (int k = 0; k < 64; k++) {
        float4 bv = *(const float4*)(sW + k * 64 + tx * 4);
#pragma unroll
        for (int r = 0; r < 8; r++) {
            float a = sX[ty * 8 + r][k];
            acc[r][0] = fmaf(a, bv.x, acc[r][0]);
            acc[r][1] = fmaf(a, bv.y, acc[r][1]);
            acc[r][2] = fmaf(a, bv.z, acc[r][2]);
            acc[r][3] = fmaf(a, bv.w, acc[r][3]);
        }
    }
    int c0 = tx * 4;
    float s0 = ssc[c0+0], s1 = ssc[c0+1], s2 = ssc[c0+2], s3 = ssc[c0+3];
    float h0 = ssh[c0+0], h1 = ssh[c0+1], h2 = ssh[c0+2], h3 = ssh[c0+3];
#pragma unroll
    for (int r = 0; r < 8; r++) {
        float4 o;
        o.x = fmaxf(fmaf(acc[r][0], s0, h0), 0.f);
        o.y = fmaxf(fmaf(acc[r][1], s1, h1), 0.f);
        o.z = fmaxf(fmaf(acc[r][2], s2, h2), 0.f);
        o.w = fmaxf(fmaf(acc[r][3], s3, h3), 0.f);
        ((float4*)g_h1)[(row0 + ty * 8 + r) * 16 + tx] = o;
    }
}

// ---------------------------------------------------------------------------
// z2 = sum_k gather_k(h1) @ w2[k]   (raw, no b2), plus per-channel sum/sumsq.
__global__ void __launch_bounds__(256) k_subm(const int* __restrict__ nbr,
                                              const float* __restrict__ W2)
{
    extern __shared__ float dyn[];
    float (*sA)[65] = (float(*)[65])dyn;     // 128x65
    float* sB = dyn + 128 * 65;              // 64x64
    int*   sIdx = (int*)(sB + 4096);         // 128
    float* sSum = (float*)(sIdx + 128);      // 64
    float* sSq  = sSum + 64;                 // 64

    int tid = threadIdx.x, tx = tid & 15, ty = tid >> 4;
    int p0 = blockIdx.x * 128;

    float acc[8][4];
#pragma unroll
    for (int r = 0; r < 8; r++) { acc[r][0]=0;acc[r][1]=0;acc[r][2]=0;acc[r][3]=0; }

    for (int k = 0; k < 9; k++) {
        __syncthreads();
        for (int i = tid; i < 1024; i += 256)
            ((float4*)sB)[i] = ((const float4*)(W2 + k * 4096))[i];
        if (tid < 128) sIdx[tid] = nbr[(p0 + tid) * 9 + k];
        __syncthreads();
        for (int e = tid; e < 2048; e += 256) {
            int r = e >> 4, s = e & 15;
            int src = sIdx[r];
            float4 v = make_float4(0.f, 0.f, 0.f, 0.f);
            if (src >= 0) v = ((const float4*)g_h1)[src * 16 + s];
            sA[r][s * 4 + 0] = v.x; sA[r][s * 4 + 1] = v.y;
            sA[r][s * 4 + 2] = v.z; sA[r][s * 4 + 3] = v.w;
        }
        __syncthreads();
#pragma unroll 4
        for (int kk = 0; kk < 64; kk++) {
            float4 bv = *(const float4*)(sB + kk * 64 + tx * 4);
#pragma unroll
            for (int r = 0; r < 8; r++) {
                float a = sA[ty * 8 + r][kk];
                acc[r][0] = fmaf(a, bv.x, acc[r][0]);
                acc[r][1] = fmaf(a, bv.y, acc[r][1]);
                acc[r][2] = fmaf(a, bv.z, acc[r][2]);
                acc[r][3] = fmaf(a, bv.w, acc[r][3]);
            }
        }
    }

    if (tid < 64) { sSum[tid] = 0.f; sSq[tid] = 0.f; }
    __syncthreads();
#pragma unroll
    for (int r = 0; r < 8; r++) {
        float4 o = make_float4(acc[r][0], acc[r][1], acc[r][2], acc[r][3]);
        ((float4*)g_z2)[(p0 + ty * 8 + r) * 16 + tx] = o;
    }
#pragma unroll
    for (int c = 0; c < 4; c++) {
        float s = 0.f, q = 0.f;
#pragma unroll
        for (int r = 0; r < 8; r++) { float v = acc[r][c]; s += v; q = fmaf(v, v, q); }
        atomicAdd(&sSum[tx * 4 + c], s);
        atomicAdd(&sSq [tx * 4 + c], q);
    }
    __syncthreads();
    if (tid < 64) {
        atomicAdd(&g_acc[4160 + tid], sSum[tid]);
        atomicAdd(&g_acc[4224 + tid], sSq[tid]);
    }
}

// ---------------------------------------------------------------------------
// out = relu(bn3(h2@w3+b3)) + bn_s(feats@ws+bs)
// h2 recomputed from z2 on the fly. Tile: 64 rows x 128 cols, grid.y picks half.
__global__ void __launch_bounds__(256) k_final(const float* __restrict__ feats,
                                               const float* __restrict__ w3,
                                               const float* __restrict__ ws,
                                               float* __restrict__ out)
{
    extern __shared__ float dyn[];
    float (*sF)[65] = (float(*)[65])dyn;                 // 64x65
    float (*sH)[65] = (float(*)[65])(dyn + 64 * 65);     // 64x65
    float* sW3 = dyn + 2 * 64 * 65;                      // 64x128
    float* sWs = sW3 + 8192;                             // 64x128
    float* p    = sWs + 8192;
    float* sc3l = p;        float* sh3l = p + 128;
    float* scsl = p + 256;  float* shsl = p + 384;
    float* ssc2 = p + 512;  float* ssh2 = p + 576;

    int tid = threadIdx.x;
    int row0 = blockIdx.x * 64;
    int bj0  = blockIdx.y * 128;

    if (tid < 128) {
        sc3l[tid] = g_sc3[bj0 + tid]; sh3l[tid] = g_sh3[bj0 + tid];
        scsl[tid] = g_scs[bj0 + tid]; shsl[tid] = g_shs[bj0 + tid];
    }
    if (tid < 64) { ssc2[tid] = g_sc2[tid]; ssh2[tid] = g_sh2[tid]; }
    __syncthreads();

    for (int e = tid; e < 1024; e += 256) {
        int r = e >> 4, s = e & 15;
        float4 v = ((const float4*)feats)[(row0 + r) * 16 + s];
        sF[r][s * 4 + 0] = v.x; sF[r][s * 4 + 1] = v.y;
        sF[r][s * 4 + 2] = v.z; sF[r][s * 4 + 3] = v.w;
        float4 z = ((const float4*)g_z2)[(row0 + r) * 16 + s];
        int c = s * 4;
        sH[r][c + 0] = fmaxf(fmaf(z.x, ssc2[c + 0], ssh2[c + 0]), 0.f);
        sH[r][c + 1] = fmaxf(fmaf(z.y, ssc2[c + 1], ssh2[c + 1]), 0.f);
        sH[r][c + 2] = fmaxf(fmaf(z.z, ssc2[c + 2], ssh2[c + 2]), 0.f);
        sH[r][c + 3] = fmaxf(fmaf(z.w, ssc2[c + 3], ssh2[c + 3]), 0.f);
    }
    for (int e = tid; e < 2048; e += 256) {
        int r = e >> 5, s = e & 31;
        ((float4*)sW3)[e] = ((const float4*)w3)[r * 64 + (bj0 >> 2) + s];
        ((float4*)sWs)[e] = ((const float4*)ws)[r * 64 + (bj0 >> 2) + s];
    }
    __syncthreads();

    int tx = tid & 31, ty = tid >> 5;
    float a1[8][4], a2[8][4];
#pragma unroll
    for (int r = 0; r < 8; r++) {
        a1[r][0]=0;a1[r][1]=0;a1[r][2]=0;a1[r][3]=0;
        a2[r][0]=0;a2[r][1]=0;a2[r][2]=0;a2[r][3]=0;
    }

#pragma unroll 4
    for (int kk = 0; kk < 64; kk++) {
        float4 b3v = *(const float4*)(sW3 + kk * 128 + tx * 4);
        float4 bsv = *(const float4*)(sWs + kk * 128 + tx * 4);
#pragma unroll
        for (int r = 0; r < 8; r++) {
            float h = sH[ty * 8 + r][kk];
            float f = sF[ty * 8 + r][kk];
            a1[r][0] = fmaf(h, b3v.x, a1[r][0]);
            a1[r][1] = fmaf(h, b3v.y, a1[r][1]);
            a1[r][2] = fmaf(h, b3v.z, a1[r][2]);
            a1[r][3] = fmaf(h, b3v.w, a1[r][3]);
            a2[r][0] = fmaf(f, bsv.x, a2[r][0]);
            a2[r][1] = fmaf(f, bsv.y, a2[r][1]);
            a2[r][2] = fmaf(f, bsv.z, a2[r][2]);
            a2[r][3] = fmaf(f, bsv.w, a2[r][3]);
        }
    }

    int c0 = tx * 4;
    float t30 = sc3l[c0+0], t31 = sc3l[c0+1], t32 = sc3l[c0+2], t33 = sc3l[c0+3];
    float u30 = sh3l[c0+0], u31 = sh3l[c0+1], u32 = sh3l[c0+2], u33 = sh3l[c0+3];
    float ts0 = scsl[c0+0], ts1 = scsl[c0+1], ts2 = scsl[c0+2], ts3 = scsl[c0+3];
    float us0 = shsl[c0+0], us1 = shsl[c0+1], us2 = shsl[c0+2], us3 = shsl[c0+3];
#pragma unroll
    for (int r = 0; r < 8; r++) {
        int row = row0 + ty * 8 + r;
        float4 o;
        o.x = fmaxf(fmaf(a1[r][0], t30, u30), 0.f) + fmaf(a2[r][0], ts0, us0);
        o.y = fmaxf(fmaf(a1[r][1], t31, u31), 0.f) + fmaf(a2[r][1], ts1, us1);
        o.z = fmaxf(fmaf(a1[r][2], t32, u32), 0.f) + fmaf(a2[r][2], ts2, us2);
        o.w = fmaxf(fmaf(a1[r][3], t33, u33), 0.f) + fmaf(a2[r][3], ts3, us3);
        ((float4*)out)[row * 64 + (bj0 >> 2) + tx] = o;
    }
}

// ---------------------------------------------------------------------------
static const int SMEM_G1   = (4096 + 128 * 65 + 128) * 4;              // 50176
static const int SMEM_SUBM = (128 * 65 + 4096 + 128 + 128) * 4;        // 50688
static const int SMEM_FIN  = (2 * 64 * 65 + 2 * 8192 + 640) * 4;       // 101376

extern "C" void kernel_launch(void* const* d_in, const int* in_sizes, int n_in,
                              void* d_out, int out_size)
{
    const float* feats = (const float*)d_in[0];
    const int*   nbr   = (const int*)d_in[1];
    const float* w1  = (const float*)d_in[2];
    const float* b1  = (const float*)d_in[3];
    const float* g1  = (const float*)d_in[4];
    const float* be1 = (const float*)d_in[5];
    const float* w2  = (const float*)d_in[6];
    const float* b2  = (const float*)d_in[7];
    const float* g2  = (const float*)d_in[8];
    const float* be2 = (const float*)d_in[9];
    const float* w3  = (const float*)d_in[10];
    const float* b3  = (const float*)d_in[11];
    const float* g3  = (const float*)d_in[12];
    const float* be3 = (const float*)d_in[13];
    const float* ws  = (const float*)d_in[14];
    const float* bs  = (const float*)d_in[15];
    const float* gs  = (const float*)d_in[16];
    const float* bes = (const float*)d_in[17];
    float* out = (float*)d_out;

    cudaFuncSetAttribute(k_gemm1, cudaFuncAttributeMaxDynamicSharedMemorySize, SMEM_G1);
    cudaFuncSetAttribute(k_subm,  cudaFuncAttributeMaxDynamicSharedMemorySize, SMEM_SUBM);
    cudaFuncSetAttribute(k_final, cudaFuncAttributeMaxDynamicSharedMemorySize, SMEM_FIN);

    // 1) zero accumulators
    k_zero<<<33, 256>>>();
    // 2) feats colsum + Gram  -> analytic BN stats for Z1 and Zs
    k_stats64<<<782, 256>>>(feats, 0);
    k_params_lin<<<1, 256>>>(0, 64,  w1, b1, g1, be1);
    k_params_lin<<<1, 256>>>(1, 256, ws, bs, gs, bes);
    // 3) h1 = relu(bn(feats@w1+b1))
    k_gemm1<<<NPTS / 128, 256, SMEM_G1>>>(feats, w1);
    // 4) z2 = subm3x3(h1) + stats
    k_subm<<<NPTS / 128, 256, SMEM_SUBM>>>(nbr, w2);
    k_params2<<<1, 64>>>(b2, g2, be2);
    // 5) h2 colsum + Gram -> analytic BN stats for Z3
    k_stats64<<<782, 256>>>(nullptr, 1);
    k_params_lin<<<1, 256>>>(2, 256, w3, b3, g3, be3);
    // 6) out = relu(bn3(h2@w3+b3)) + bn_s(feats@ws+bs)
    dim3 gf(NPTS / 64, 2);
    k_final<<<gf, 256, SMEM_FIN>>>(feats, w3, ws, out);

    (void)in_sizes; (void)n_in; (void)out_size;
    (void)b1; // b1 used in params; silence nothing
}

// round 16
// speedup vs baseline: 1.9059x; 1.9059x over previous
#include <cuda_runtime.h>

#define NPTS   800000
#define EPSV   1e-5f

// ---------------- scratch (device globals; no allocation allowed) ----------
__device__ float g_h1[NPTS * 64];   // relu(bn(feats@w1+b1))
__device__ float g_z2[NPTS * 64];   // subm3x3(h1) (raw, no b2)

// accumulators, zeroed at the start of every launch
// [0,64) colsum(feats) [64,4160) gram(feats)
// [4160,4224) colsum(z2) [4224,4288) colsumsq(z2)
// [4288,4352) colsum(h2) [4352,8448) gram(h2)
__device__ float g_acc[8448];

__device__ float g_sc1[64],  g_sh1[64];
__device__ float g_scs[256], g_shs[256];
__device__ float g_sc2[64],  g_sh2[64];
__device__ float g_sc3[256], g_sh3[256];

// ---------------------------------------------------------------------------
__device__ __forceinline__ unsigned f2tf(float f)
{
    unsigned u;
    asm("cvt.rna.tf32.f32 %0, %1;" : "=r"(u) : "f"(f));
    return u;
}

// D += A(16x8,row) * B(8x8,col)  tf32, fp32 accum
__device__ __forceinline__ void mma8(float* c,
                                     unsigned a0, unsigned a1, unsigned a2, unsigned a3,
                                     unsigned b0, unsigned b1)
{
    asm volatile(
        "mma.sync.aligned.m16n8k8.row.col.f32.tf32.tf32.f32 "
        "{%0,%1,%2,%3}, {%4,%5,%6,%7}, {%8,%9}, {%0,%1,%2,%3};"
        : "+f"(c[0]), "+f"(c[1]), "+f"(c[2]), "+f"(c[3])
        : "r"(a0), "r"(a1), "r"(a2), "r"(a3), "r"(b0), "r"(b1));
}

// ---------------------------------------------------------------------------
__global__ void k_zero()
{
    int i = blockIdx.x * 256 + threadIdx.x;
    if (i < 8448) g_acc[i] = 0.0f;
}

// ---------------------------------------------------------------------------
// colsum + Gram of a [N,64] matrix via tf32 mma.
// mode 0: X = feats (argument).  mode 1: X = relu(g_z2*sc2+sh2)  (h2).
__global__ void __launch_bounds__(256) k_stats64(const float* __restrict__ X, int mode)
{
    __shared__ unsigned sX[32 * 72];        // 32 rows x 64 ch, stride 72 (conflict-free)
    __shared__ float ssc[64], ssh[64], sSum[64];

    float* outSum  = mode ? &g_acc[4288] : &g_acc[0];
    float* outGram = mode ? &g_acc[4352] : &g_acc[64];
    const float* src = mode ? g_z2 : X;

    int tid = threadIdx.x;
    if (tid < 64) {
        sSum[tid] = 0.f;
        ssc[tid] = mode ? g_sc2[tid] : 0.f;
        ssh[tid] = mode ? g_sh2[tid] : 0.f;
    }
    __syncthreads();

    int lane = tid & 31, w = tid >> 5;
    int grp = lane >> 2, tig = lane & 3;
    int m0 = (w >> 1) * 16, n0 = (w & 1) * 32;
    int s = tid & 15, r0 = tid >> 4;

    float acc[4][4];
#pragma unroll
    for (int i = 0; i < 4; i++) { acc[i][0]=0;acc[i][1]=0;acc[i][2]=0;acc[i][3]=0; }
    float cs[4] = {0.f, 0.f, 0.f, 0.f};

    int rowBase = blockIdx.x * 1024;
    for (int chunk = 0; chunk < 1024; chunk += 32) {
        __syncthreads();
#pragma unroll
        for (int rr = 0; rr < 2; rr++) {
            int r = rowBase + chunk + r0 + rr * 16;
            float4 v = make_float4(0.f, 0.f, 0.f, 0.f);
            if (r < NPTS) v = reinterpret_cast<const float4*>(src)[r * 16 + s];
            if (mode) {
                int c = s * 4;
                v.x = fmaxf(fmaf(v.x, ssc[c + 0], ssh[c + 0]), 0.f);
                v.y = fmaxf(fmaf(v.y, ssc[c + 1], ssh[c + 1]), 0.f);
                v.z = fmaxf(fmaf(v.z, ssc[c + 2], ssh[c + 2]), 0.f);
                v.w = fmaxf(fmaf(v.w, ssc[c + 3], ssh[c + 3]), 0.f);
            }
            if (r >= NPTS) { v.x = 0.f; v.y = 0.f; v.z = 0.f; v.w = 0.f; }  // mask pad rows AFTER transform
            unsigned u0 = f2tf(v.x), u1 = f2tf(v.y), u2 = f2tf(v.z), u3 = f2tf(v.w);
            int base = (r0 + rr * 16) * 72 + s * 4;
            sX[base + 0] = u0; sX[base + 1] = u1; sX[base + 2] = u2; sX[base + 3] = u3;
            cs[0] += __uint_as_float(u0); cs[1] += __uint_as_float(u1);
            cs[2] += __uint_as_float(u2); cs[3] += __uint_as_float(u3);
        }
        __syncthreads();
        // Gram += sX^T * sX  : A[m][k]=sX[k][m], B[k][n]=sX[k][n], K=32
#pragma unroll
        for (int kk = 0; kk < 4; kk++) {
            int kb = kk * 8;
            unsigned a0 = sX[(kb + tig) * 72 + m0 + grp];
            unsigned a1 = sX[(kb + tig) * 72 + m0 + grp + 8];
            unsigned a2 = sX[(kb + tig + 4) * 72 + m0 + grp];
            unsigned a3 = sX[(kb + tig + 4) * 72 + m0 + grp + 8];
#pragma unroll
            for (int j = 0; j < 4; j++) {
                unsigned b0 = sX[(kb + tig) * 72 + n0 + j * 8 + grp];
                unsigned b1 = sX[(kb + tig + 4) * 72 + n0 + j * 8 + grp];
                mma8(acc[j], a0, a1, a2, a3, b0, b1);
            }
        }
    }
#pragma unroll
    for (int j = 0; j < 4; j++) {
        int row = m0 + grp, col = n0 + j * 8 + tig * 2;
        atomicAdd(&outGram[row * 64 + col],           acc[j][0]);
        atomicAdd(&outGram[row * 64 + col + 1],       acc[j][1]);
        atomicAdd(&outGram[(row + 8) * 64 + col],     acc[j][2]);
        atomicAdd(&outGram[(row + 8) * 64 + col + 1], acc[j][3]);
    }
    atomicAdd(&sSum[s * 4 + 0], cs[0]); atomicAdd(&sSum[s * 4 + 1], cs[1]);
    atomicAdd(&sSum[s * 4 + 2], cs[2]); atomicAdd(&sSum[s * 4 + 3], cs[3]);
    __syncthreads();
    if (tid < 64) atomicAdd(&outSum[tid], sSum[tid]);
}

// ---------------------------------------------------------------------------
// Analytic BN params for Z = X@w + b from Gram/colsum of X. (unchanged)
__global__ void k_params_lin(int which, int J,
                             const float* __restrict__ w, const float* __restrict__ b,
                             const float* __restrict__ g, const float* __restrict__ be)
{
    __shared__ float sG[4096];
    __shared__ float sMu[64];
    const float* gram = (which == 2) ? &g_acc[4352] : &g_acc[64];
    const float* csum = (which == 2) ? &g_acc[4288] : &g_acc[0];
    float* sc = (which == 0) ? g_sc1 : (which == 1) ? g_scs : g_sc3;
    float* sh = (which == 0) ? g_sh1 : (which == 1) ? g_shs : g_sh3;

    int tid = threadIdx.x;
    for (int i = tid; i < 4096; i += blockDim.x) sG[i] = gram[i];
    if (tid < 64) sMu[tid] = csum[tid] * (1.0f / (float)NPTS);
    __syncthreads();

    for (int j = tid; j < J; j += blockDim.x) {
        float wj[64];
        for (int c = 0; c < 64; c++) wj[c] = w[c * J + j];
        float mw = 0.f;
        for (int c = 0; c < 64; c++) mw = fmaf(sMu[c], wj[c], mw);
        float q = 0.f;
        for (int c = 0; c < 64; c++) {
            float t = 0.f;
            for (int d = 0; d < 64; d++) t = fmaf(sG[c * 64 + d], wj[d], t);
            q = fmaf(t, wj[c], q);
        }
        q *= (1.0f / (float)NPTS);
        float bj = b[j];
        float m = mw + bj;
        float ex2 = q + 2.f * bj * mw + bj * bj;
        float var = ex2 - m * m;
        float scale = g[j] * rsqrtf(var + EPSV);
        sc[j] = scale;
        sh[j] = be[j] + (bj - m) * scale;
    }
}

__global__ void k_params2(const float* __restrict__ b2, const float* __restrict__ g2,
                          const float* __restrict__ be2)
{
    int j = threadIdx.x;
    if (j < 64) {
        float inv = 1.0f / (float)NPTS;
        float mean = g_acc[4160 + j] * inv;
        float var  = g_acc[4224 + j] * inv - mean * mean;
        float scale = g2[j] * rsqrtf(var + EPSV);
        g_sc2[j] = scale;
        g_sh2[j] = be2[j] - mean * scale;
        (void)b2;
    }
}

// ---------------------------------------------------------------------------
// h1 = relu(bn(feats@w1+b1))  via tf32 mma. Tile 128x64, 256 thr (8 warps).
__global__ void __launch_bounds__(256) k_gemm1(const float* __restrict__ X,
                                               const float* __restrict__ W)
{
    extern __shared__ unsigned dynu[];
    unsigned* sA = dynu;                    // 128 x 64, stride 68
    unsigned* sW = dynu + 128 * 68;         // 64 x 64,  stride 72
    float* ssc = (float*)(sW + 64 * 72);
    float* ssh = ssc + 64;

    int tid = threadIdx.x;
    if (tid < 64) { ssc[tid] = g_sc1[tid]; ssh[tid] = g_sh1[tid]; }
    for (int e = tid; e < 1024; e += 256) {
        int k = e >> 4, s = e & 15;
        float4 v = ((const float4*)W)[e];
        int base = k * 72 + s * 4;
        sW[base + 0] = f2tf(v.x); sW[base + 1] = f2tf(v.y);
        sW[base + 2] = f2tf(v.z); sW[base + 3] = f2tf(v.w);
    }
    int row0 = blockIdx.x * 128;
    for (int e = tid; e < 2048; e += 256) {
        int r = e >> 4, s = e & 15;
        float4 v = ((const float4*)X)[(row0 + r) * 16 + s];
        int base = r * 68 + s * 4;
        sA[base + 0] = f2tf(v.x); sA[base + 1] = f2tf(v.y);
        sA[base + 2] = f2tf(v.z); sA[base + 3] = f2tf(v.w);
    }
    __syncthreads();

    int lane = tid & 31, w = tid >> 5;
    int grp = lane >> 2, tig = lane & 3;
    int m0 = w * 16;

    float acc[8][4];
#pragma unroll
    for (int j = 0; j < 8; j++) { acc[j][0]=0;acc[j][1]=0;acc[j][2]=0;acc[j][3]=0; }

#pragma unroll
    for (int kk = 0; kk < 8; kk++) {
        int kb = kk * 8;
        unsigned a0 = sA[(m0 + grp) * 68 + kb + tig];
        unsigned a1 = sA[(m0 + grp + 8) * 68 + kb + tig];
        unsigned a2 = sA[(m0 + grp) * 68 + kb + tig + 4];
        unsigned a3 = sA[(m0 + grp + 8) * 68 + kb + tig + 4];
#pragma unroll
        for (int j = 0; j < 8; j++) {
            unsigned b0 = sW[(kb + tig) * 72 + j * 8 + grp];
            unsigned b1 = sW[(kb + tig + 4) * 72 + j * 8 + grp];
            mma8(acc[j], a0, a1, a2, a3, b0, b1);
        }
    }
#pragma unroll
    for (int j = 0; j < 8; j++) {
        int col = j * 8 + tig * 2;
        float s0 = ssc[col], s1 = ssc[col + 1], h0 = ssh[col], h1 = ssh[col + 1];
        int r = row0 + m0 + grp;
        float2 o;
        o.x = fmaxf(fmaf(acc[j][0], s0, h0), 0.f);
        o.y = fmaxf(fmaf(acc[j][1], s1, h1), 0.f);
        *(float2*)&g_h1[r * 64 + col] = o;
        o.x = fmaxf(fmaf(acc[j][2], s0, h0), 0.f);
        o.y = fmaxf(fmaf(acc[j][3], s1, h1), 0.f);
        *(float2*)&g_h1[(r + 8) * 64 + col] = o;
    }
}

// ---------------------------------------------------------------------------
// z2 = sum_k gather_k(h1) @ w2[k]  via tf32 mma + per-channel sum/sumsq.
__global__ void __launch_bounds__(256) k_subm(const int* __restrict__ nbr,
                                              const float* __restrict__ W2)
{
    extern __shared__ unsigned dynu[];
    unsigned* sA = dynu;                    // 128 x 64, stride 68
    unsigned* sW = dynu + 128 * 68;         // 64 x 64,  stride 72
    int*   sIdx = (int*)(sW + 64 * 72);     // 128
    float* sSum = (float*)(sIdx + 128);     // 64
    float* sSq  = sSum + 64;                // 64

    int tid = threadIdx.x;
    int lane = tid & 31, w = tid >> 5;
    int grp = lane >> 2, tig = lane & 3;
    int m0 = w * 16;
    int p0 = blockIdx.x * 128;

    if (tid < 64) { sSum[tid] = 0.f; sSq[tid] = 0.f; }

    float acc[8][4];
#pragma unroll
    for (int j = 0; j < 8; j++) { acc[j][0]=0;acc[j][1]=0;acc[j][2]=0;acc[j][3]=0; }

    for (int k9 = 0; k9 < 9; k9++) {
        __syncthreads();   // prior mma done with sA/sW
        for (int e = tid; e < 1024; e += 256) {
            int k = e >> 4, s = e & 15;
            float4 v = ((const float4*)(W2 + k9 * 4096))[e];
            int base = k * 72 + s * 4;
            sW[base + 0] = f2tf(v.x); sW[base + 1] = f2tf(v.y);
            sW[base + 2] = f2tf(v.z); sW[base + 3] = f2tf(v.w);
        }
        if (tid < 128) sIdx[tid] = nbr[(p0 + tid) * 9 + k9];
        __syncthreads();   // sIdx ready
        for (int e = tid; e < 2048; e += 256) {
            int r = e >> 4, s = e & 15;
            int src = sIdx[r];
            float4 v = make_float4(0.f, 0.f, 0.f, 0.f);
            if (src >= 0) v = ((const float4*)g_h1)[src * 16 + s];
            int base = r * 68 + s * 4;
            sA[base + 0] = f2tf(v.x); sA[base + 1] = f2tf(v.y);
            sA[base + 2] = f2tf(v.z); sA[base + 3] = f2tf(v.w);
        }
        __syncthreads();   // sA + sW ready
#pragma unroll
        for (int kk = 0; kk < 8; kk++) {
            int kb = kk * 8;
            unsigned a0 = sA[(m0 + grp) * 68 + kb + tig];
            unsigned a1 = sA[(m0 + grp + 8) * 68 + kb + tig];
            unsigned a2 = sA[(m0 + grp) * 68 + kb + tig + 4];
            unsigned a3 = sA[(m0 + grp + 8) * 68 + kb + tig + 4];
#pragma unroll
            for (int j = 0; j < 8; j++) {
                unsigned b0 = sW[(kb + tig) * 72 + j * 8 + grp];
                unsigned b1 = sW[(kb + tig + 4) * 72 + j * 8 + grp];
                mma8(acc[j], a0, a1, a2, a3, b0, b1);
            }
        }
    }

    // write z2 + channel stats
#pragma unroll
    for (int j = 0; j < 8; j++) {
        int col = j * 8 + tig * 2;
        int r = p0 + m0 + grp;
        *(float2*)&g_z2[r * 64 + col]       = make_float2(acc[j][0], acc[j][1]);
        *(float2*)&g_z2[(r + 8) * 64 + col] = make_float2(acc[j][2], acc[j][3]);
        float s0 = acc[j][0] + acc[j][2];
        float s1 = acc[j][1] + acc[j][3];
        float q0 = fmaf(acc[j][0], acc[j][0], acc[j][2] * acc[j][2]);
        float q1 = fmaf(acc[j][1], acc[j][1], acc[j][3] * acc[j][3]);
#pragma unroll
        for (int off = 16; off >= 4; off >>= 1) {
            s0 += __shfl_down_sync(0xffffffffu, s0, off);
            s1 += __shfl_down_sync(0xffffffffu, s1, off);
            q0 += __shfl_down_sync(0xffffffffu, q0, off);
            q1 += __shfl_down_sync(0xffffffffu, q1, off);
        }
        if (lane < 4) {
            atomicAdd(&sSum[j * 8 + lane * 2 + 0], s0);
            atomicAdd(&sSum[j * 8 + lane * 2 + 1], s1);
            atomicAdd(&sSq [j * 8 + lane * 2 + 0], q0);
            atomicAdd(&sSq [j * 8 + lane * 2 + 1], q1);
        }
    }
    __syncthreads();
    if (tid < 64) {
        atomicAdd(&g_acc[4160 + tid], sSum[tid]);
        atomicAdd(&g_acc[4224 + tid], sSq[tid]);
    }
}

// ---------------------------------------------------------------------------
// out = relu(bn3(h2@w3+b3)) + bn_s(feats@ws+bs)   via tf32 mma.
// Tile 128 rows x 128 cols, 512 thr (16 warps); grid.y selects col half.
__global__ void __launch_bounds__(512) k_final(const float* __restrict__ feats,
                                               const float* __restrict__ w3,
                                               const float* __restrict__ ws,
                                               float* __restrict__ out)
{
    extern __shared__ unsigned dynu[];
    unsigned* sH  = dynu;                     // 128 x 64, stride 68
    unsigned* sF  = dynu + 128 * 68;          // 128 x 64, stride 68
    unsigned* sW3 = dynu + 2 * 128 * 68;      // 64 x 128, stride 136
    unsigned* sWs = sW3 + 64 * 136;           // 64 x 128, stride 136
    float* p    = (float*)(sWs + 64 * 136);
    float* sc3l = p;        float* sh3l = p + 128;
    float* scsl = p + 256;  float* shsl = p + 384;
    float* ssc2 = p + 512;  float* ssh2 = p + 576;

    int tid = threadIdx.x;
    int row0 = blockIdx.x * 128;
    int bj0  = blockIdx.y * 128;

    if (tid < 128) {
        sc3l[tid] = g_sc3[bj0 + tid]; sh3l[tid] = g_sh3[bj0 + tid];
        scsl[tid] = g_scs[bj0 + tid]; shsl[tid] = g_shs[bj0 + tid];
    }
    if (tid < 64) { ssc2[tid] = g_sc2[tid]; ssh2[tid] = g_sh2[tid]; }
    __syncthreads();

    for (int e = tid; e < 2048; e += 512) {
        int r = e >> 4, s = e & 15;
        float4 v = ((const float4*)feats)[(row0 + r) * 16 + s];
        int base = r * 68 + s * 4;
        sF[base + 0] = f2tf(v.x); sF[base + 1] = f2tf(v.y);
        sF[base + 2] = f2tf(v.z); sF[base + 3] = f2tf(v.w);
        float4 z = ((const float4*)g_z2)[(row0 + r) * 16 + s];
        int c = s * 4;
        sH[base + 0] = f2tf(fmaxf(fmaf(z.x, ssc2[c + 0], ssh2[c + 0]), 0.f));
        sH[base + 1] = f2tf(fmaxf(fmaf(z.y, ssc2[c + 1], ssh2[c + 1]), 0.f));
        sH[base + 2] = f2tf(fmaxf(fmaf(z.z, ssc2[c + 2], ssh2[c + 2]), 0.f));
        sH[base + 3] = f2tf(fmaxf(fmaf(z.w, ssc2[c + 3], ssh2[c + 3]), 0.f));
    }
    for (int e = tid; e < 2048; e += 512) {
        int k = e >> 5, s = e & 31;
        float4 v = ((const float4*)w3)[k * 64 + (bj0 >> 2) + s];
        int base = k * 136 + s * 4;
        sW3[base + 0] = f2tf(v.x); sW3[base + 1] = f2tf(v.y);
        sW3[base + 2] = f2tf(v.z); sW3[base + 3] = f2tf(v.w);
        float4 u = ((const float4*)ws)[k * 64 + (bj0 >> 2) + s];
        sWs[base + 0] = f2tf(u.x); sWs[base + 1] = f2tf(u.y);
        sWs[base + 2] = f2tf(u.z); sWs[base + 3] = f2tf(u.w);
    }
    __syncthreads();

    int lane = tid & 31, w = tid >> 5;
    int grp = lane >> 2, tig = lane & 3;
    int m0 = (w >> 1) * 16;
    int n0 = (w & 1) * 64;

    float a1[8][4], a2[8][4];
#pragma unroll
    for (int j = 0; j < 8; j++) {
        a1[j][0]=0;a1[j][1]=0;a1[j][2]=0;a1[j][3]=0;
        a2[j][0]=0;a2[j][1]=0;a2[j][2]=0;a2[j][3]=0;
    }

#pragma unroll
    for (int kk = 0; kk < 8; kk++) {
        int kb = kk * 8;
        unsigned h0 = sH[(m0 + grp) * 68 + kb + tig];
        unsigned h1 = sH[(m0 + grp + 8) * 68 + kb + tig];
        unsigned h2 = sH[(m0 + grp) * 68 + kb + tig + 4];
        unsigned h3 = sH[(m0 + grp + 8) * 68 + kb + tig + 4];
        unsigned f0 = sF[(m0 + grp) * 68 + kb + tig];
        unsigned f1 = sF[(m0 + grp + 8) * 68 + kb + tig];
        unsigned f2 = sF[(m0 + grp) * 68 + kb + tig + 4];
        unsigned f3 = sF[(m0 + grp + 8) * 68 + kb + tig + 4];
#pragma unroll
        for (int j = 0; j < 8; j++) {
            unsigned b0 = sW3[(kb + tig) * 136 + n0 + j * 8 + grp];
            unsigned b1 = sW3[(kb + tig + 4) * 136 + n0 + j * 8 + grp];
            mma8(a1[j], h0, h1, h2, h3, b0, b1);
            unsigned c0 = sWs[(kb + tig) * 136 + n0 + j * 8 + grp];
            unsigned c1 = sWs[(kb + tig + 4) * 136 + n0 + j * 8 + grp];
            mma8(a2[j], f0, f1, f2, f3, c0, c1);
        }
    }

#pragma unroll
    for (int j = 0; j < 8; j++) {
        int col = n0 + j * 8 + tig * 2;           // within 128-col block
        float t0 = sc3l[col], t1 = sc3l[col + 1];
        float u0 = sh3l[col], u1 = sh3l[col + 1];
        float v0 = scsl[col], v1 = scsl[col + 1];
        float x0 = shsl[col], x1 = shsl[col + 1];
        int r = row0 + m0 + grp;
        float2 o;
        o.x = fmaxf(fmaf(a1[j][0], t0, u0), 0.f) + fmaf(a2[j][0], v0, x0);
        o.y = fmaxf(fmaf(a1[j][1], t1, u1), 0.f) + fmaf(a2[j][1], v1, x1);
        *(float2*)&out[r * 256 + bj0 + col] = o;
        o.x = fmaxf(fmaf(a1[j][2], t0, u0), 0.f) + fmaf(a2[j][2], v0, x0);
        o.y = fmaxf(fmaf(a1[j][3], t1, u1), 0.f) + fmaf(a2[j][3], v1, x1);
        *(float2*)&out[(r + 8) * 256 + bj0 + col] = o;
    }
}

// ---------------------------------------------------------------------------
static const int SMEM_G1   = (128 * 68 + 64 * 72 + 128) * 4;             // 53760
static const int SMEM_SUBM = (128 * 68 + 64 * 72) * 4 + 128 * 4 + 128 * 4; // 54272
static const int SMEM_FIN  = (2 * 128 * 68 + 2 * 64 * 136 + 640) * 4;    // 141824

extern "C" void kernel_launch(void* const* d_in, const int* in_sizes, int n_in,
                              void* d_out, int out_size)
{
    const float* feats = (const float*)d_in[0];
    const int*   nbr   = (const int*)d_in[1];
    const float* w1  = (const float*)d_in[2];
    const float* b1  = (const float*)d_in[3];
    const float* g1  = (const float*)d_in[4];
    const float* be1 = (const float*)d_in[5];
    const float* w2  = (const float*)d_in[6];
    const float* b2  = (const float*)d_in[7];
    const float* g2  = (const float*)d_in[8];
    const float* be2 = (const float*)d_in[9];
    const float* w3  = (const float*)d_in[10];
    const float* b3  = (const float*)d_in[11];
    const float* g3  = (const float*)d_in[12];
    const float* be3 = (const float*)d_in[13];
    const float* ws  = (const float*)d_in[14];
    const float* bs  = (const float*)d_in[15];
    const float* gs  = (const float*)d_in[16];
    const float* bes = (const float*)d_in[17];
    float* out = (float*)d_out;

    cudaFuncSetAttribute(k_gemm1, cudaFuncAttributeMaxDynamicSharedMemorySize, SMEM_G1);
    cudaFuncSetAttribute(k_subm,  cudaFuncAttributeMaxDynamicSharedMemorySize, SMEM_SUBM);
    cudaFuncSetAttribute(k_final, cudaFuncAttributeMaxDynamicSharedMemorySize, SMEM_FIN);

    k_zero<<<33, 256>>>();
    k_stats64<<<782, 256>>>(feats, 0);
    k_params_lin<<<1, 256>>>(0, 64,  w1, b1, g1, be1);
    k_params_lin<<<1, 256>>>(1, 256, ws, bs, gs, bes);
    k_gemm1<<<NPTS / 128, 256, SMEM_G1>>>(feats, w1);
    k_subm<<<NPTS / 128, 256, SMEM_SUBM>>>(nbr, w2);
    k_params2<<<1, 64>>>(b2, g2, be2);
    k_stats64<<<782, 256>>>(nullptr, 1);
    k_params_lin<<<1, 256>>>(2, 256, w3, b3, g3, be3);
    dim3 gf(NPTS / 128, 2);
    k_final<<<gf, 512, SMEM_FIN>>>(feats, w3, ws, out);

    (void)in_sizes; (void)n_in; (void)out_size;
}